// round 2
// baseline (speedup 1.0000x reference)
#include <cuda_runtime.h>

#define B_  16
#define C_  512
#define HW_ 4096

// ---------------- scratch (static device globals: alloc-free) ----------------
__device__ float g_Ws[(size_t)B_ * C_ * C_];   // 16.8 MB
__device__ float g_v[2][B_ * C_];
__device__ float g_u[B_ * HW_];
__device__ float g_unorm[B_];

// ---------------- GEMM: Ws[b] = X_b * X_b^T (symmetric, upper tiles only) ----
#define BM 128
#define BN 128
#define BK 32

__device__ __forceinline__ void tile_pair(int t, int& tm, int& tn) {
    // enumerate upper-triangular 4x4 tile pairs, t in [0,10)
    if (t < 4)      { tm = 0; tn = t; }
    else if (t < 7) { tm = 1; tn = t - 3; }
    else if (t < 9) { tm = 2; tn = t - 5; }
    else            { tm = 3; tn = 3; }
}

__global__ __launch_bounds__(256, 2)
void gemm_ws(const float* __restrict__ x) {
    int tm, tn;
    tile_pair(blockIdx.x, tm, tn);
    const int b = blockIdx.y;
    const float* __restrict__ X = x + (size_t)b * C_ * HW_;
    float* __restrict__ Ws = g_Ws + (size_t)b * C_ * C_;
    const int c0 = tm * BM;
    const int d0 = tn * BN;

    __shared__ float As[BK][BM + 4];   // [k][m], +4 pad for store conflicts
    __shared__ float Bs[BK][BN + 4];

    const int tid  = threadIdx.x;
    const int lrow = tid >> 3;          // 0..31
    const int lk4  = (tid & 7) * 4;     // 0,4,...,28

    const int tm8 = (tid >> 4) * 8;     // 0..120
    const int tn8 = (tid & 15) * 8;

    float acc[8][8];
    #pragma unroll
    for (int i = 0; i < 8; i++)
        #pragma unroll
        for (int j = 0; j < 8; j++) acc[i][j] = 0.f;

    for (int k0 = 0; k0 < HW_; k0 += BK) {
        #pragma unroll
        for (int i = 0; i < 4; i++) {
            const int row = lrow + i * 32;
            float4 a = *(const float4*)&X[(size_t)(c0 + row) * HW_ + k0 + lk4];
            As[lk4 + 0][row] = a.x; As[lk4 + 1][row] = a.y;
            As[lk4 + 2][row] = a.z; As[lk4 + 3][row] = a.w;
            float4 bb = *(const float4*)&X[(size_t)(d0 + row) * HW_ + k0 + lk4];
            Bs[lk4 + 0][row] = bb.x; Bs[lk4 + 1][row] = bb.y;
            Bs[lk4 + 2][row] = bb.z; Bs[lk4 + 3][row] = bb.w;
        }
        __syncthreads();

        #pragma unroll
        for (int kk = 0; kk < BK; kk++) {
            float a[8], bv[8];
            *(float4*)&a[0]  = *(const float4*)&As[kk][tm8];
            *(float4*)&a[4]  = *(const float4*)&As[kk][tm8 + 4];
            *(float4*)&bv[0] = *(const float4*)&Bs[kk][tn8];
            *(float4*)&bv[4] = *(const float4*)&Bs[kk][tn8 + 4];
            #pragma unroll
            for (int i = 0; i < 8; i++)
                #pragma unroll
                for (int j = 0; j < 8; j++)
                    acc[i][j] += a[i] * bv[j];
        }
        __syncthreads();
    }

    // store tile (coalesced float4 along d)
    #pragma unroll
    for (int i = 0; i < 8; i++) {
        const int c = c0 + tm8 + i;
        float4 s0 = make_float4(acc[i][0], acc[i][1], acc[i][2], acc[i][3]);
        float4 s1 = make_float4(acc[i][4], acc[i][5], acc[i][6], acc[i][7]);
        *(float4*)&Ws[(size_t)c * C_ + d0 + tn8]     = s0;
        *(float4*)&Ws[(size_t)c * C_ + d0 + tn8 + 4] = s1;
    }
    // mirror to lower triangle
    if (tm != tn) {
        #pragma unroll
        for (int i = 0; i < 8; i++) {
            const int c = c0 + tm8 + i;
            #pragma unroll
            for (int j = 0; j < 8; j++)
                Ws[(size_t)(d0 + tn8 + j) * C_ + c] = acc[i][j];
        }
    }
}

// ---------------- power iteration step: vout = 2^-13 * Ws^T vin (= Ws vin) ---
__global__ void piter(int srcExt, const float* __restrict__ vext,
                      int srcPar, int dstPar) {
    const int b  = blockIdx.y;
    const int d0 = blockIdx.x * 128;
    const int tx = threadIdx.x;   // 0..127
    const int ty = threadIdx.y;   // 0..3

    const float* __restrict__ vin = srcExt ? (vext + b * C_) : &g_v[srcPar][b * C_];

    __shared__ float vs[C_];
    __shared__ float partial[4][128];

    for (int i = ty * 128 + tx; i < C_; i += 512) vs[i] = vin[i];
    __syncthreads();

    const float* __restrict__ Wsb = g_Ws + (size_t)b * C_ * C_;
    const int d = d0 + tx;
    float acc = 0.f;
    #pragma unroll 8
    for (int cc = 0; cc < 128; cc++) {
        const int c = ty * 128 + cc;
        acc += Wsb[(size_t)c * C_ + d] * vs[c];
    }
    partial[ty][tx] = acc;
    __syncthreads();
    if (ty == 0) {
        float s = partial[0][tx] + partial[1][tx] + partial[2][tx] + partial[3][tx];
        g_v[dstPar][b * C_ + d] = s * 0.0001220703125f;   // * 2^-13 (direction-preserving)
    }
}

// ---------------- final normalize of v; also zero unorm accumulator ----------
__global__ void normalize_v(int par) {
    const int b = blockIdx.x;
    float* v = &g_v[par][b * C_];
    const int t = threadIdx.x;   // 512
    float val = v[t];
    float s = val * val;
    #pragma unroll
    for (int o = 16; o; o >>= 1) s += __shfl_xor_sync(0xFFFFFFFFu, s, o);
    __shared__ float red[16];
    if ((t & 31) == 0) red[t >> 5] = s;
    __syncthreads();
    __shared__ float inv;
    if (t == 0) {
        float tot = 0.f;
        #pragma unroll
        for (int i = 0; i < 16; i++) tot += red[i];
        inv = rsqrtf(tot);
        g_unorm[b] = 0.f;
    }
    __syncthreads();
    v[t] = val * inv;
}

// ---------------- u[b][n] = sum_c x[b][c][n] * v[c]; accumulate ||u||^2 ------
__global__ void compute_u(const float* __restrict__ x, int par) {
    const int b = blockIdx.y;
    const int n = blockIdx.x * 256 + threadIdx.x;

    __shared__ float vs[C_];
    for (int i = threadIdx.x; i < C_; i += 256) vs[i] = g_v[par][b * C_ + i];
    __syncthreads();

    const float* __restrict__ X = x + (size_t)b * C_ * HW_;
    float acc = 0.f;
    #pragma unroll 8
    for (int c = 0; c < C_; c++)
        acc += X[(size_t)c * HW_ + n] * vs[c];
    g_u[b * HW_ + n] = acc;

    float s = acc * acc;
    #pragma unroll
    for (int o = 16; o; o >>= 1) s += __shfl_xor_sync(0xFFFFFFFFu, s, o);
    __shared__ float red[8];
    if ((threadIdx.x & 31) == 0) red[threadIdx.x >> 5] = s;
    __syncthreads();
    if (threadIdx.x == 0) {
        float tot = 0.f;
        #pragma unroll
        for (int i = 0; i < 8; i++) tot += red[i];
        atomicAdd(&g_unorm[b], tot);
    }
}

// ---------------- out = x + (u/||u||) v^T  (float4 streaming) ----------------
__global__ void fuse_out(const float* __restrict__ x, float* __restrict__ out, int par) {
    const size_t idx4 = (size_t)blockIdx.x * 256 + threadIdx.x;
    const size_t base = idx4 * 4;
    const int b = (int)(base >> 21);          // C_*HW_ = 2^21
    const int c = (int)((base >> 12) & 511);
    const int n = (int)(base & 4095);

    const float inv = rsqrtf(g_unorm[b]);
    const float vc  = g_v[par][b * C_ + c] * inv;

    float4 xv = *(const float4*)&x[base];
    float4 uu = *(const float4*)&g_u[b * HW_ + n];
    float4 o;
    o.x = xv.x + uu.x * vc;
    o.y = xv.y + uu.y * vc;
    o.z = xv.z + uu.z * vc;
    o.w = xv.w + uu.w * vc;
    *(float4*)&out[base] = o;
}

// ---------------- launch --------------------------------------------------
extern "C" void kernel_launch(void* const* d_in, const int* in_sizes, int n_in,
                              void* d_out, int out_size) {
    (void)in_sizes; (void)n_in; (void)out_size;
    const float* x = (const float*)d_in[0];
    const float* v = (const float*)d_in[1];
    float* out = (float*)d_out;

    gemm_ws<<<dim3(10, B_), 256>>>(x);

    // 10 power-iteration steps, ping-pong parity; final result lands in parity 0
    piter<<<dim3(4, B_), dim3(128, 4)>>>(1, v, 0, 1);
    for (int i = 1; i < 10; i++)
        piter<<<dim3(4, B_), dim3(128, 4)>>>(0, nullptr, i & 1, (i + 1) & 1);

    normalize_v<<<B_, C_>>>(0);
    compute_u<<<dim3(HW_ / 256, B_), 256>>>(x, 0);
    fuse_out<<<(B_ * C_ * HW_) / (4 * 256), 256>>>(x, out, 0);
}

// round 11
// speedup vs baseline: 3.3508x; 3.3508x over previous
#include <cuda_runtime.h>
#include <cuda_bf16.h>
#include <cstdint>

#define B_  16
#define C_  512
#define HW_ 4096

// ---------------- scratch (static device globals: alloc-free) ----------------
__device__ float g_Ws[(size_t)B_ * C_ * C_];                 // 16.8 MB fp32
__device__ __nv_bfloat16 g_xb[(size_t)B_ * C_ * HW_];        // 67 MB bf16 copy of x
__device__ float g_v[2][B_ * C_];
__device__ float g_u[B_ * HW_];
__device__ float g_unorm[B_];

__device__ __forceinline__ uint32_t smem_u32(const void* p) {
    uint32_t a;
    asm("{ .reg .u64 t; cvta.to.shared.u64 t, %1; cvt.u32.u64 %0, t; }" : "=r"(a) : "l"(p));
    return a;
}

// ---------------- x -> bf16 ----------------
__global__ void to_bf16(const float* __restrict__ x) {
    size_t i = ((size_t)blockIdx.x * 256 + threadIdx.x) * 8;
    float4 a = *(const float4*)&x[i];
    float4 c = *(const float4*)&x[i + 4];
    __nv_bfloat162* o = (__nv_bfloat162*)&g_xb[i];
    o[0] = __floats2bfloat162_rn(a.x, a.y);
    o[1] = __floats2bfloat162_rn(a.z, a.w);
    o[2] = __floats2bfloat162_rn(c.x, c.y);
    o[3] = __floats2bfloat162_rn(c.z, c.w);
}

// ---------------- HMMA GEMM: Ws[b] = Xb Xb^T (upper-tri tiles only) ----------
__device__ __forceinline__ void tile_pair(int t, int& tm, int& tn) {
    if (t < 4)      { tm = 0; tn = t; }
    else if (t < 7) { tm = 1; tn = t - 3; }
    else if (t < 9) { tm = 2; tn = t - 5; }
    else            { tm = 3; tn = 3; }
}

#define BKH 32
#define LDA 40        // padded row length (bf16 elems): 80B rows, conflict-free ldmatrix

__global__ void __launch_bounds__(256, 1) gemm_ws_mma() {
    __shared__ __nv_bfloat16 As[2][128 * LDA];   // 10 KB per stage
    __shared__ __nv_bfloat16 Bs[2][128 * LDA];

    int tm, tn;
    tile_pair(blockIdx.x, tm, tn);
    const int b = blockIdx.y;
    const __nv_bfloat16* __restrict__ Xb = g_xb + (size_t)b * C_ * HW_;
    float* __restrict__ Ws = g_Ws + (size_t)b * C_ * C_;
    const int c0 = tm * 128;
    const int d0 = tn * 128;

    const int tid = threadIdx.x;
    const int lane = tid & 31;
    const int warp = tid >> 5;
    const int wm = warp >> 2;       // 0..1  -> 64-row slab
    const int wn = warp & 3;        // 0..3  -> 32-col slab

    const uint32_t aBase = smem_u32(As);
    const uint32_t bBase = smem_u32(Bs);

    float acc[4][4][4];
    #pragma unroll
    for (int ma = 0; ma < 4; ma++)
        #pragma unroll
        for (int na = 0; na < 4; na++)
            #pragma unroll
            for (int q = 0; q < 4; q++) acc[ma][na][q] = 0.f;

    // stage load: 128 rows x 32 bf16 (4 x 16B per row) for A and B
    auto issue = [&](int s, int k0) {
        #pragma unroll
        for (int i = 0; i < 2; i++) {
            const int t = tid + i * 256;          // 0..511
            const int row = t >> 2;
            const int seg = t & 3;
            const uint32_t so = (uint32_t)(s * 128 * LDA + row * LDA + seg * 8) * 2;
            asm volatile("cp.async.cg.shared.global [%0], [%1], 16;"
                         :: "r"(aBase + so), "l"(Xb + (size_t)(c0 + row) * HW_ + k0 + seg * 8));
            asm volatile("cp.async.cg.shared.global [%0], [%1], 16;"
                         :: "r"(bBase + so), "l"(Xb + (size_t)(d0 + row) * HW_ + k0 + seg * 8));
        }
        asm volatile("cp.async.commit_group;");
    };

    issue(0, 0);
    const int NCHUNK = HW_ / BKH;                 // 128
    for (int i = 0; i < NCHUNK; i++) {
        const int s = i & 1;
        if (i + 1 < NCHUNK) {
            issue(s ^ 1, (i + 1) * BKH);
            asm volatile("cp.async.wait_group 1;");
        } else {
            asm volatile("cp.async.wait_group 0;");
        }
        __syncthreads();

        #pragma unroll
        for (int ks = 0; ks < 2; ks++) {          // two k16 steps per chunk
            uint32_t a[4][4], bbf[4][2];
            #pragma unroll
            for (int ma = 0; ma < 4; ma++) {
                const int row = wm * 64 + ma * 16 + (lane & 15);
                const uint32_t addr = aBase +
                    (uint32_t)(s * 128 * LDA + row * LDA + ks * 16 + (lane >> 4) * 8) * 2;
                asm volatile("ldmatrix.sync.aligned.m8n8.x4.shared.b16 {%0,%1,%2,%3}, [%4];"
                             : "=r"(a[ma][0]), "=r"(a[ma][1]), "=r"(a[ma][2]), "=r"(a[ma][3])
                             : "r"(addr));
            }
            #pragma unroll
            for (int na = 0; na < 4; na++) {
                const int row = wn * 32 + na * 8 + (lane & 7);
                const uint32_t addr = bBase +
                    (uint32_t)(s * 128 * LDA + row * LDA + ks * 16 + ((lane >> 3) & 1) * 8) * 2;
                asm volatile("ldmatrix.sync.aligned.m8n8.x2.shared.b16 {%0,%1}, [%2];"
                             : "=r"(bbf[na][0]), "=r"(bbf[na][1]) : "r"(addr));
            }
            #pragma unroll
            for (int ma = 0; ma < 4; ma++)
                #pragma unroll
                for (int na = 0; na < 4; na++)
                    asm volatile(
                        "mma.sync.aligned.m16n8k16.row.col.f32.bf16.bf16.f32 "
                        "{%0,%1,%2,%3}, {%4,%5,%6,%7}, {%8,%9}, {%0,%1,%2,%3};"
                        : "+f"(acc[ma][na][0]), "+f"(acc[ma][na][1]),
                          "+f"(acc[ma][na][2]), "+f"(acc[ma][na][3])
                        : "r"(a[ma][0]), "r"(a[ma][1]), "r"(a[ma][2]), "r"(a[ma][3]),
                          "r"(bbf[na][0]), "r"(bbf[na][1]));
        }
        __syncthreads();
    }

    // epilogue: register fragments straight to gmem (float2 per atom-row)
    #pragma unroll
    for (int ma = 0; ma < 4; ma++) {
        const int row = c0 + wm * 64 + ma * 16 + (lane >> 2);
        #pragma unroll
        for (int na = 0; na < 4; na++) {
            const int col = d0 + wn * 32 + na * 8 + (lane & 3) * 2;
            *(float2*)&Ws[(size_t)row * C_ + col] =
                make_float2(acc[ma][na][0], acc[ma][na][1]);
            *(float2*)&Ws[(size_t)(row + 8) * C_ + col] =
                make_float2(acc[ma][na][2], acc[ma][na][3]);
        }
    }
}

// ---------------- mirror upper -> lower triangle (6 off-diag tiles) ----------
__global__ void mirror_ws() {
    const int pm[6] = {0, 0, 0, 1, 1, 2};
    const int pn[6] = {1, 2, 3, 2, 3, 3};
    const int c0 = pm[blockIdx.x] * 128;
    const int d0 = pn[blockIdx.x] * 128;
    float* __restrict__ Ws = g_Ws + (size_t)blockIdx.y * C_ * C_;

    __shared__ float sm[32][129];
    for (int sl = 0; sl < 4; sl++) {
        for (int t = threadIdx.x; t < 1024; t += 256) {
            const int r = t >> 5, c4 = (t & 31) * 4;
            float4 v = *(const float4*)&Ws[(size_t)(c0 + sl * 32 + r) * C_ + d0 + c4];
            sm[r][c4 + 0] = v.x; sm[r][c4 + 1] = v.y;
            sm[r][c4 + 2] = v.z; sm[r][c4 + 3] = v.w;
        }
        __syncthreads();
        for (int t = threadIdx.x; t < 1024; t += 256) {
            const int rr = t >> 3, q = (t & 7) * 4;
            float4 v = make_float4(sm[q + 0][rr], sm[q + 1][rr], sm[q + 2][rr], sm[q + 3][rr]);
            *(float4*)&Ws[(size_t)(d0 + rr) * C_ + c0 + sl * 32 + q] = v;
        }
        __syncthreads();
    }
}

// ---------------- power iteration: vout = 2^-13 * Ws v  (256 CTAs) -----------
__global__ void piter(int srcExt, const float* __restrict__ vext,
                      int srcPar, int dstPar) {
    const int b = blockIdx.y;
    const int d = blockIdx.x * 32 + threadIdx.x;
    const int ty = threadIdx.y;                    // 0..7
    __shared__ float vs[C_];
    __shared__ float part[8][32];

    const float* __restrict__ vin = srcExt ? (vext + b * C_) : &g_v[srcPar][b * C_];
    for (int i = ty * 32 + threadIdx.x; i < C_; i += 256) vs[i] = vin[i];
    __syncthreads();

    const float* __restrict__ Wsb = g_Ws + (size_t)b * C_ * C_;
    float acc = 0.f;
    #pragma unroll 16
    for (int cc = 0; cc < 64; cc++) {
        const int c = ty * 64 + cc;
        acc += Wsb[(size_t)c * C_ + d] * vs[c];
    }
    part[ty][threadIdx.x] = acc;
    __syncthreads();
    if (ty == 0) {
        float s = 0.f;
        #pragma unroll
        for (int t = 0; t < 8; t++) s += part[t][threadIdx.x];
        g_v[dstPar][b * C_ + d] = s * 0.0001220703125f;   // * 2^-13, direction-preserving
    }
}

// ---------------- final normalize of v; zero unorm ----------------
__global__ void normalize_v(int par) {
    const int b = blockIdx.x;
    float* v = &g_v[par][b * C_];
    const int t = threadIdx.x;   // 512
    float val = v[t];
    float s = val * val;
    #pragma unroll
    for (int o = 16; o; o >>= 1) s += __shfl_xor_sync(0xFFFFFFFFu, s, o);
    __shared__ float red[16];
    if ((t & 31) == 0) red[t >> 5] = s;
    __syncthreads();
    __shared__ float inv;
    if (t == 0) {
        float tot = 0.f;
        #pragma unroll
        for (int i = 0; i < 16; i++) tot += red[i];
        inv = rsqrtf(tot);
        g_unorm[b] = 0.f;
    }
    __syncthreads();
    v[t] = val * inv;
}

// ---------------- u = X^T v (bf16 x), accumulate ||u||^2 ----------------
__global__ void compute_u(int par) {
    const int b = blockIdx.y;
    const int n2 = blockIdx.x * 256 + threadIdx.x;      // bf16x2 pair index

    __shared__ float vs[C_];
    for (int i = threadIdx.x; i < C_; i += 256) vs[i] = g_v[par][b * C_ + i];
    __syncthreads();

    const __nv_bfloat162* __restrict__ X2 =
        (const __nv_bfloat162*)(g_xb + (size_t)b * C_ * HW_);
    float ax = 0.f, ay = 0.f;
    #pragma unroll 8
    for (int c = 0; c < C_; c++) {
        float2 f = __bfloat1622float2(X2[(size_t)c * (HW_ / 2) + n2]);
        ax += f.x * vs[c];
        ay += f.y * vs[c];
    }
    const int n = n2 * 2;
    *(float2*)&g_u[b * HW_ + n] = make_float2(ax, ay);

    float s = ax * ax + ay * ay;
    #pragma unroll
    for (int o = 16; o; o >>= 1) s += __shfl_xor_sync(0xFFFFFFFFu, s, o);
    __shared__ float red[8];
    if ((threadIdx.x & 31) == 0) red[threadIdx.x >> 5] = s;
    __syncthreads();
    if (threadIdx.x == 0) {
        float tot = 0.f;
        #pragma unroll
        for (int i = 0; i < 8; i++) tot += red[i];
        atomicAdd(&g_unorm[b], tot);
    }
}

// ---------------- out = x + (u/||u||) v^T ----------------
__global__ void fuse_out(const float* __restrict__ x, float* __restrict__ out, int par) {
    const size_t idx4 = (size_t)blockIdx.x * 256 + threadIdx.x;
    const size_t base = idx4 * 4;
    const int b = (int)(base >> 21);
    const int c = (int)((base >> 12) & 511);
    const int n = (int)(base & 4095);

    const float inv = rsqrtf(g_unorm[b]);
    const float vc  = g_v[par][b * C_ + c] * inv;

    float4 xv = *(const float4*)&x[base];
    float4 uu = *(const float4*)&g_u[b * HW_ + n];
    float4 o;
    o.x = xv.x + uu.x * vc;
    o.y = xv.y + uu.y * vc;
    o.z = xv.z + uu.z * vc;
    o.w = xv.w + uu.w * vc;
    *(float4*)&out[base] = o;
}

// ---------------- launch ----------------
extern "C" void kernel_launch(void* const* d_in, const int* in_sizes, int n_in,
                              void* d_out, int out_size) {
    (void)in_sizes; (void)n_in; (void)out_size;
    const float* x = (const float*)d_in[0];
    const float* v = (const float*)d_in[1];
    float* out = (float*)d_out;

    to_bf16<<<(B_ * C_ * HW_) / (8 * 256), 256>>>(x);
    gemm_ws_mma<<<dim3(10, B_), 256>>>();
    mirror_ws<<<dim3(6, B_), 256>>>();

    piter<<<dim3(16, B_), dim3(32, 8)>>>(1, v, 0, 1);
    for (int i = 1; i < 10; i++)
        piter<<<dim3(16, B_), dim3(32, 8)>>>(0, nullptr, i & 1, (i + 1) & 1);

    normalize_v<<<B_, C_>>>(0);
    compute_u<<<dim3(HW_ / 512, B_), 256>>>(0);
    fuse_out<<<(B_ * C_ * HW_) / (4 * 256), 256>>>(x, out, 0);
}